// round 10
// baseline (speedup 1.0000x reference)
#include <cuda_runtime.h>
#include <math.h>
#include <stdint.h>

#define MAXB 64
#define MAXP 8732
#define MAXO 16
#define MSPLIT 32                          // P-splits in match kernel
#define TP 256                             // priors per loss block
#define MB 1024                            // mine block threads
#define NIT ((MAXP + MB - 1) / MB)         // 9 keys per mine thread
#define ACC_SCALE 67108864.0               // 2^26 fixed-point for deterministic atomics

// ---- scratch (static __device__; no runtime allocation) ----
__device__ unsigned long long g_keypart[MAXB * MAXO * MSPLIT]; // plain stores, no init
__device__ float              g_mined[MAXB * MAXP];
__device__ int                g_num_pos[MAXB];
__device__ float              g_negsum[MAXB];
__device__ unsigned long long g_acc_l[MAXB];
__device__ unsigned long long g_acc_c[MAXB];
__device__ unsigned int       g_done;

// ---------------------------------------------------------------------------
// Per-truth best prior over a P-chunk (min-p tie-break); partial written with
// a plain store into g_keypart (reduced later in loss_kernel). bx==0 block
// also zeroes the per-batch accumulators (loss/mine are stream-ordered after).
template <int OO>
__global__ void __launch_bounds__(256)
match_kernel_t(const float* __restrict__ priors,
               const float* __restrict__ targets,
               int P) {
    int b = blockIdx.y;
    int bx = blockIdx.x;
    int tid = threadIdx.x;
    __shared__ float sh_t[OO * 5];
    __shared__ unsigned long long sh_key[OO];

    if (bx == 0 && tid == 0) {
        g_num_pos[b] = 0;
        g_acc_l[b] = 0ull;
        g_acc_c[b] = 0ull;
        if (b == 0) g_done = 0u;
    }
    if (tid < OO * 5) sh_t[tid] = targets[b * OO * 5 + tid];
    if (tid < OO)     sh_key[tid] = 0ull;
    __syncthreads();

    int chunk = (P + gridDim.x - 1) / gridDim.x;
    int p0 = bx * chunk;
    int p1 = min(p0 + chunk, P);

    unsigned long long lkey[OO];
#pragma unroll
    for (int o = 0; o < OO; o++) lkey[o] = 0ull;

    const float4* pr4 = (const float4*)priors;
    for (int p = p0 + tid; p < p1; p += blockDim.x) {
        float4 pr = pr4[p];
        float px0 = pr.x - pr.z * 0.5f, py0 = pr.y - pr.w * 0.5f;
        float px1 = pr.x + pr.z * 0.5f, py1 = pr.y + pr.w * 0.5f;
        float areaP = pr.z * pr.w;
#pragma unroll
        for (int o = 0; o < OO; o++) {
            float t0 = sh_t[o * 5 + 0], t1 = sh_t[o * 5 + 1];
            float t2 = sh_t[o * 5 + 2], t3 = sh_t[o * 5 + 3];
            float ltx = fmaxf(t0, px0), lty = fmaxf(t1, py0);
            float rbx = fminf(t2, px1), rby = fminf(t3, py1);
            float iw = fmaxf(rbx - ltx, 0.f), ih = fmaxf(rby - lty, 0.f);
            float inter = iw * ih;
            float areaT = (t2 - t0) * (t3 - t1);
            float ov = __fdividef(inter, areaT + areaP - inter);
            unsigned long long key =
                ((unsigned long long)__float_as_uint(ov) << 32) |
                (unsigned long long)(0xFFFFFFFFu - (unsigned)p);  // tie -> min p
            if (key > lkey[o]) lkey[o] = key;
        }
    }
#pragma unroll
    for (int o = 0; o < OO; o++) {
#pragma unroll
        for (int off = 16; off; off >>= 1) {
            unsigned long long other = __shfl_down_sync(0xFFFFFFFFu, lkey[o], off);
            if (other > lkey[o]) lkey[o] = other;
        }
    }
    if ((tid & 31) == 0) {
#pragma unroll
        for (int o = 0; o < OO; o++) atomicMax(&sh_key[o], lkey[o]);
    }
    __syncthreads();
    if (tid < OO)
        g_keypart[(b * MAXO + tid) * MSPLIT + bx] = sh_key[tid];
}

// Generic fallback (O != 8)
__global__ void __launch_bounds__(256)
match_kernel_gen(const float* __restrict__ priors,
                 const float* __restrict__ targets,
                 int P, int O) {
    int b = blockIdx.y;
    int bx = blockIdx.x;
    int tid = threadIdx.x;
    __shared__ float sh_t[MAXO * 5];
    __shared__ unsigned long long sh_key[MAXO];

    if (bx == 0 && tid == 0) {
        g_num_pos[b] = 0;
        g_acc_l[b] = 0ull;
        g_acc_c[b] = 0ull;
        if (b == 0) g_done = 0u;
    }
    if (tid < MAXO) sh_key[tid] = 0ull;   // all MAXO slots stored below
    if (tid < O * 5) sh_t[tid] = targets[b * O * 5 + tid];
    __syncthreads();

    int chunk = (P + gridDim.x - 1) / gridDim.x;
    int p0 = bx * chunk;
    int p1 = min(p0 + chunk, P);

    const float4* pr4 = (const float4*)priors;
    for (int p = p0 + tid; p < p1; p += blockDim.x) {
        float4 pr = pr4[p];
        float px0 = pr.x - pr.z * 0.5f, py0 = pr.y - pr.w * 0.5f;
        float px1 = pr.x + pr.z * 0.5f, py1 = pr.y + pr.w * 0.5f;
        float areaP = pr.z * pr.w;
        for (int o = 0; o < O; o++) {
            float t0 = sh_t[o * 5 + 0], t1 = sh_t[o * 5 + 1];
            float t2 = sh_t[o * 5 + 2], t3 = sh_t[o * 5 + 3];
            float ltx = fmaxf(t0, px0), lty = fmaxf(t1, py0);
            float rbx = fminf(t2, px1), rby = fminf(t3, py1);
            float iw = fmaxf(rbx - ltx, 0.f), ih = fmaxf(rby - lty, 0.f);
            float inter = iw * ih;
            float areaT = (t2 - t0) * (t3 - t1);
            float ov = __fdividef(inter, areaT + areaP - inter);
            unsigned long long key =
                ((unsigned long long)__float_as_uint(ov) << 32) |
                (unsigned long long)(0xFFFFFFFFu - (unsigned)p);
            atomicMax(&sh_key[o], key);
        }
    }
    __syncthreads();
    if (tid < MAXO)
        g_keypart[(b * MAXO + tid) * MSPLIT + bx] = sh_key[tid];
}

// ---------------------------------------------------------------------------
// Thread-per-prior fused loss: conf tile staged in SMEM (coalesced), each
// thread does OO IoUs + override + logsumexp over C SMEM values + smooth-L1.
template <int CC, int OO>
__global__ void __launch_bounds__(TP)
loss_kernel(const float* __restrict__ loc_data,
            const float* __restrict__ conf_data,
            const float* __restrict__ priors,
            const float* __restrict__ targets,
            int P, int C) {
    int b = blockIdx.y;
    int tid = threadIdx.x;
    int p0 = blockIdx.x * TP;
    int cnt = min(TP, P - p0);

    __shared__ float sconf[TP * CC];
    __shared__ float sh_t[OO * 5];
    __shared__ unsigned sh_win[OO];
    __shared__ float s_rl[TP / 32], s_rc[TP / 32];
    __shared__ int s_rn[TP / 32];

    if (tid < OO * 5) sh_t[tid] = targets[b * OO * 5 + tid];
    if (tid < OO) {
        unsigned long long kmax = 0ull;
        const unsigned long long* kp = g_keypart + (b * MAXO + tid) * MSPLIT;
#pragma unroll
        for (int s = 0; s < MSPLIT; s++) {
            unsigned long long v = kp[s];
            if (v > kmax) kmax = v;
        }
        sh_win[tid] = 0xFFFFFFFFu - (unsigned)(kmax & 0xFFFFFFFFull);
    }

    {
        size_t base = ((size_t)b * P + p0) * C;
        int tot = cnt * C;
        for (int j = tid; j < tot; j += TP)
            sconf[j] = conf_data[base + j];
    }
    __syncthreads();

    float ll = 0.f, cpos = 0.f;
    int np = 0;

    if (tid < cnt) {
        int p = p0 + tid;
        size_t bp = (size_t)b * P + p;
        float4 pr = ((const float4*)priors)[p];
        float px0 = pr.x - pr.z * 0.5f, py0 = pr.y - pr.w * 0.5f;
        float px1 = pr.x + pr.z * 0.5f, py1 = pr.y + pr.w * 0.5f;
        float areaP = pr.z * pr.w;

        float bestv = -1.f; int ti = 0; int ovr = -1;
#pragma unroll
        for (int o = 0; o < OO; o++) {
            float t0 = sh_t[o * 5 + 0], t1 = sh_t[o * 5 + 1];
            float t2 = sh_t[o * 5 + 2], t3 = sh_t[o * 5 + 3];
            float ltx = fmaxf(t0, px0), lty = fmaxf(t1, py0);
            float rbx = fminf(t2, px1), rby = fminf(t3, py1);
            float iw = fmaxf(rbx - ltx, 0.f), ih = fmaxf(rby - lty, 0.f);
            float inter = iw * ih;
            float areaT = (t2 - t0) * (t3 - t1);
            float ov = __fdividef(inter, areaT + areaP - inter);
            if (ov > bestv) { bestv = ov; ti = o; }      // first (lowest) o on tie
            if (sh_win[o] == (unsigned)p) ovr = o;       // last (highest) o wins
        }
        if (ovr >= 0) { bestv = 2.0f; ti = ovr; }
        int conf_t = (bestv >= 0.5f) ? (int)sh_t[ti * 5 + 4] + 1 : 0;
        bool pos = (conf_t > 0);

        const float* row = sconf + tid * C;
        float m = row[0];
        for (int c = 1; c < C; c++) m = fmaxf(m, row[c]);
        float e = 0.f;
        for (int c = 0; c < C; c++) e += __expf(row[c] - m);
        float lc = m + __logf(e) - row[conf_t];

        g_mined[bp] = pos ? 0.f : lc;
        if (pos) {
            cpos = lc;
            np = 1;
            float mx0 = sh_t[ti * 5 + 0], my0 = sh_t[ti * 5 + 1];
            float mx1 = sh_t[ti * 5 + 2], my1 = sh_t[ti * 5 + 3];
            float g0 = ((mx0 + mx1) * 0.5f - pr.x) / (0.1f * pr.z);
            float g1 = ((my0 + my1) * 0.5f - pr.y) / (0.1f * pr.w);
            float g2 = __logf(fmaxf((mx1 - mx0) / pr.z, 1e-8f)) / 0.2f;
            float g3 = __logf(fmaxf((my1 - my0) / pr.w, 1e-8f)) / 0.2f;
            float4 L = ((const float4*)loc_data)[bp];
            float Ld[4] = {L.x, L.y, L.z, L.w};
            float g4[4] = {g0, g1, g2, g3};
#pragma unroll
            for (int i = 0; i < 4; i++) {
                float d = Ld[i] - g4[i];
                float ad = fabsf(d);
                ll += (ad < 1.f) ? 0.5f * d * d : ad - 0.5f;
            }
        }
    }

    int lane = tid & 31;
#pragma unroll
    for (int off = 16; off; off >>= 1) {
        ll   += __shfl_down_sync(0xFFFFFFFFu, ll, off);
        cpos += __shfl_down_sync(0xFFFFFFFFu, cpos, off);
        np   += __shfl_down_sync(0xFFFFFFFFu, np, off);
    }
    if (lane == 0) { s_rl[tid >> 5] = ll; s_rc[tid >> 5] = cpos; s_rn[tid >> 5] = np; }
    __syncthreads();
    if (tid == 0) {
        float tl = 0.f, tc = 0.f; int tn = 0;
#pragma unroll
        for (int w = 0; w < TP / 32; w++) { tl += s_rl[w]; tc += s_rc[w]; tn += s_rn[w]; }
        if (tl != 0.f)
            atomicAdd(&g_acc_l[b], (unsigned long long)(long long)llrint((double)tl * ACC_SCALE));
        if (tc != 0.f)
            atomicAdd(&g_acc_c[b], (unsigned long long)(long long)llrint((double)tc * ACC_SCALE));
        if (tn) atomicAdd(&g_num_pos[b], tn);
    }
}

// ---------------------------------------------------------------------------
// Per-batch radix-select of top-k mined conf losses. Keys in registers,
// warp-aggregated shared histogram, warp-0 register suffix-scan.
__global__ void __launch_bounds__(MB, 1)
mine_kernel(float* __restrict__ out, int P, int B) {
    int b = blockIdx.x;
    int tid = threadIdx.x;
    int lane = tid & 31;

    __shared__ int hist[257];          // [256] = sentinel for invalid lanes
    __shared__ unsigned s_prefix;
    __shared__ int s_kk;
    __shared__ float s_red[MB / 32];
    __shared__ int s_last;

    // keys in registers (values >= 0: bits are order-preserving)
    unsigned key[NIT];
    bool own[NIT];
    const float* mv = g_mined + (size_t)b * P;
#pragma unroll
    for (int i = 0; i < NIT; i++) {
        int p = i * MB + tid;
        own[i] = (p < P);
        key[i] = own[i] ? __float_as_uint(mv[p]) : 0u;
    }

    int np = g_num_pos[b];
    int k = min(3 * np, P - np);
    float negsum = 0.f;

    if (k > 0) {
        unsigned prefix = 0, pmask = 0;
        int kk = k;
        for (int shift = 24; shift >= 0; shift -= 8) {
            if (tid < 257) hist[tid] = 0;
            __syncthreads();
            // warp-aggregated histogram: one atomic per distinct bin per warp
#pragma unroll
            for (int i = 0; i < NIT; i++) {
                bool valid = own[i] && ((key[i] & pmask) == prefix);
                unsigned bin = valid ? ((key[i] >> shift) & 0xFFu) : 256u;
                unsigned peers = __match_any_sync(0xFFFFFFFFu, bin);
                if (valid && lane == (__ffs(peers) - 1))
                    atomicAdd(&hist[bin], (int)__popc(peers));
            }
            __syncthreads();
            // warp-0 register suffix scan over 256 bins (lane owns 8 bins)
            if (tid < 32) {
                int base = tid * 8;
                int v[8], suff[8];
#pragma unroll
                for (int i = 0; i < 8; i++) v[i] = hist[base + i];
                int run = 0;
#pragma unroll
                for (int i = 7; i >= 0; i--) { run += v[i]; suff[i] = run; }
                int x = run;
#pragma unroll
                for (int off = 1; off < 32; off <<= 1) {
                    int y = __shfl_down_sync(0xFFFFFFFFu, x, off);
                    if (tid + off < 32) x += y;
                }
                int above = x - run;      // sum over lanes > tid
#pragma unroll
                for (int i = 0; i < 8; i++) {
                    int ss  = suff[i] + above;
                    int ssn = (i < 7) ? suff[i + 1] + above : above;
                    if (ss >= kk && ssn < kk) {
                        s_prefix = prefix | ((unsigned)(base + i) << shift);
                        s_kk = kk - ssn;
                    }
                }
            }
            __syncthreads();
            prefix = s_prefix;
            kk = s_kk;
            pmask |= 0xFFu << shift;
        }

        float lsum = 0.f;
#pragma unroll
        for (int i = 0; i < NIT; i++)
            if (own[i] && key[i] > prefix) lsum += __uint_as_float(key[i]);
#pragma unroll
        for (int off = 16; off; off >>= 1)
            lsum += __shfl_xor_sync(0xFFFFFFFFu, lsum, off);
        if (lane == 0) s_red[tid >> 5] = lsum;
        __syncthreads();
        if (tid == 0) {
            float tot = 0.f;
#pragma unroll
            for (int i = 0; i < MB / 32; i++) tot += s_red[i];
            negsum = tot + (float)kk * __uint_as_float(prefix);
        }
    }
    if (tid == 0) {
        g_negsum[b] = negsum;
        __threadfence();
        unsigned done = atomicAdd(&g_done, 1u);
        s_last = (done == (unsigned)(B - 1)) ? 1 : 0;
    }
    __syncthreads();
    if (s_last && tid < 32) {
        double ll = 0.0, lc = 0.0;
        int N = 0;
        for (int bb = tid; bb < B; bb += 32) {
            ll += (double)(long long)g_acc_l[bb];
            lc += (double)(long long)g_acc_c[bb];
            lc += (double)g_negsum[bb] * ACC_SCALE;
            N += g_num_pos[bb];
        }
#pragma unroll
        for (int off = 16; off; off >>= 1) {
            ll += __shfl_down_sync(0xFFFFFFFFu, ll, off);
            lc += __shfl_down_sync(0xFFFFFFFFu, lc, off);
            N  += __shfl_down_sync(0xFFFFFFFFu, N, off);
        }
        if (tid == 0) {
            double fN = (double)N * ACC_SCALE;
            out[0] = (float)(ll / fN);
            out[1] = (float)(lc / fN);
        }
    }
}

// ---------------------------------------------------------------------------
extern "C" void kernel_launch(void* const* d_in, const int* in_sizes, int n_in,
                              void* d_out, int out_size) {
    const float* loc     = (const float*)d_in[0];
    const float* conf    = (const float*)d_in[1];
    const float* priors  = (const float*)d_in[2];
    const float* targets = (const float*)d_in[3];

    int P = in_sizes[2] / 4;
    int B = in_sizes[0] / (P * 4);
    int C = in_sizes[1] / (B * P);
    int O = in_sizes[3] / (B * 5);
    float* out = (float*)d_out;

    dim3 mgrid(MSPLIT, B);
    if (O == 8)
        match_kernel_t<8><<<mgrid, 256>>>(priors, targets, P);
    else
        match_kernel_gen<<<mgrid, 256>>>(priors, targets, P, O);

    dim3 gridB((P + TP - 1) / TP, B);
    if (O == 8 && C == 21)
        loss_kernel<21, 8><<<gridB, TP>>>(loc, conf, priors, targets, P, C);
    else if (C <= 32 && O <= 8)
        loss_kernel<32, 8><<<gridB, TP>>>(loc, conf, priors, targets, P, C);
    else
        loss_kernel<64, MAXO><<<gridB, TP>>>(loc, conf, priors, targets, P, C);

    mine_kernel<<<B, MB>>>(out, P, B);
}

// round 11
// speedup vs baseline: 1.0839x; 1.0839x over previous
#include <cuda_runtime.h>
#include <math.h>
#include <stdint.h>

#define MAXB 64
#define MAXP 8732
#define MAXO 16
#define MSPLIT 16                          // P-splits in match kernel
#define TP 256                             // priors per loss block
#define MB 1024                            // mine block threads
#define NIT ((MAXP + MB - 1) / MB)         // 9 keys per mine thread
#define HP 264                             // padded per-warp hist row (ints)
#define ACC_SCALE 67108864.0               // 2^26 fixed-point for deterministic atomics

// ---- scratch (static __device__; no runtime allocation) ----
__device__ unsigned long long g_keypart[MAXB * MAXO * MSPLIT]; // plain stores, no init
__device__ float              g_mined[MAXB * MAXP];
__device__ int                g_num_pos[MAXB];
__device__ float              g_negsum[MAXB];
__device__ unsigned long long g_acc_l[MAXB];
__device__ unsigned long long g_acc_c[MAXB];
__device__ unsigned int       g_done;

// ---------------------------------------------------------------------------
// Per-truth best prior over a P-chunk (min-p tie-break). Truths live in
// registers; in-loop tracking is (float, int); u64 keys built only at tail.
template <int OO>
__global__ void __launch_bounds__(256)
match_kernel_t(const float* __restrict__ priors,
               const float* __restrict__ targets,
               int P) {
    int b = blockIdx.y;
    int bx = blockIdx.x;
    int tid = threadIdx.x;
    __shared__ float sh_t[OO * 5];
    __shared__ unsigned long long sh_key[OO];

    if (bx == 0 && tid == 0) {
        g_num_pos[b] = 0;
        g_acc_l[b] = 0ull;
        g_acc_c[b] = 0ull;
        if (b == 0) g_done = 0u;
    }
    if (tid < OO * 5) sh_t[tid] = targets[b * OO * 5 + tid];
    if (tid < OO)     sh_key[tid] = 0ull;
    __syncthreads();

    // truths to registers
    float T0[OO], T1[OO], T2[OO], T3[OO], TA[OO];
#pragma unroll
    for (int o = 0; o < OO; o++) {
        T0[o] = sh_t[o * 5 + 0];
        T1[o] = sh_t[o * 5 + 1];
        T2[o] = sh_t[o * 5 + 2];
        T3[o] = sh_t[o * 5 + 3];
        TA[o] = (T2[o] - T0[o]) * (T3[o] - T1[o]);
    }

    int chunk = (P + gridDim.x - 1) / gridDim.x;
    int p0 = bx * chunk;
    int p1 = min(p0 + chunk, P);

    float bv[OO];
    int bp_[OO];
#pragma unroll
    for (int o = 0; o < OO; o++) { bv[o] = -1.f; bp_[o] = 0; }

    const float4* pr4 = (const float4*)priors;
    for (int p = p0 + tid; p < p1; p += blockDim.x) {
        float4 pr = pr4[p];
        float px0 = pr.x - pr.z * 0.5f, py0 = pr.y - pr.w * 0.5f;
        float px1 = pr.x + pr.z * 0.5f, py1 = pr.y + pr.w * 0.5f;
        float areaP = pr.z * pr.w;
#pragma unroll
        for (int o = 0; o < OO; o++) {
            float ltx = fmaxf(T0[o], px0), lty = fmaxf(T1[o], py0);
            float rbx = fminf(T2[o], px1), rby = fminf(T3[o], py1);
            float iw = fmaxf(rbx - ltx, 0.f), ih = fmaxf(rby - lty, 0.f);
            float inter = iw * ih;
            float ov = __fdividef(inter, TA[o] + areaP - inter);
            if (ov > bv[o]) { bv[o] = ov; bp_[o] = p; }   // ascending p -> min-p tie
        }
    }

    // build keys, warp-reduce, shared atomic, store partial
#pragma unroll
    for (int o = 0; o < OO; o++) {
        unsigned long long key = (bv[o] < 0.f) ? 0ull :
            (((unsigned long long)__float_as_uint(bv[o]) << 32) |
             (unsigned long long)(0xFFFFFFFFu - (unsigned)bp_[o]));
#pragma unroll
        for (int off = 16; off; off >>= 1) {
            unsigned long long other = __shfl_down_sync(0xFFFFFFFFu, key, off);
            if (other > key) key = other;
        }
        if ((tid & 31) == 0) atomicMax(&sh_key[o], key);
    }
    __syncthreads();
    if (tid < OO)
        g_keypart[(b * MAXO + tid) * MSPLIT + bx] = sh_key[tid];
}

// Generic fallback (O != 8)
__global__ void __launch_bounds__(256)
match_kernel_gen(const float* __restrict__ priors,
                 const float* __restrict__ targets,
                 int P, int O) {
    int b = blockIdx.y;
    int bx = blockIdx.x;
    int tid = threadIdx.x;
    __shared__ float sh_t[MAXO * 5];
    __shared__ unsigned long long sh_key[MAXO];

    if (bx == 0 && tid == 0) {
        g_num_pos[b] = 0;
        g_acc_l[b] = 0ull;
        g_acc_c[b] = 0ull;
        if (b == 0) g_done = 0u;
    }
    if (tid < MAXO) sh_key[tid] = 0ull;
    if (tid < O * 5) sh_t[tid] = targets[b * O * 5 + tid];
    __syncthreads();

    int chunk = (P + gridDim.x - 1) / gridDim.x;
    int p0 = bx * chunk;
    int p1 = min(p0 + chunk, P);

    const float4* pr4 = (const float4*)priors;
    for (int p = p0 + tid; p < p1; p += blockDim.x) {
        float4 pr = pr4[p];
        float px0 = pr.x - pr.z * 0.5f, py0 = pr.y - pr.w * 0.5f;
        float px1 = pr.x + pr.z * 0.5f, py1 = pr.y + pr.w * 0.5f;
        float areaP = pr.z * pr.w;
        for (int o = 0; o < O; o++) {
            float t0 = sh_t[o * 5 + 0], t1 = sh_t[o * 5 + 1];
            float t2 = sh_t[o * 5 + 2], t3 = sh_t[o * 5 + 3];
            float ltx = fmaxf(t0, px0), lty = fmaxf(t1, py0);
            float rbx = fminf(t2, px1), rby = fminf(t3, py1);
            float iw = fmaxf(rbx - ltx, 0.f), ih = fmaxf(rby - lty, 0.f);
            float inter = iw * ih;
            float areaT = (t2 - t0) * (t3 - t1);
            float ov = __fdividef(inter, areaT + areaP - inter);
            unsigned long long key =
                ((unsigned long long)__float_as_uint(ov) << 32) |
                (unsigned long long)(0xFFFFFFFFu - (unsigned)p);
            atomicMax(&sh_key[o], key);
        }
    }
    __syncthreads();
    if (tid < MAXO)
        g_keypart[(b * MAXO + tid) * MSPLIT + bx] = sh_key[tid];
}

// ---------------------------------------------------------------------------
// Thread-per-prior fused loss: conf tile staged in SMEM (coalesced), each
// thread does OO IoUs + override + logsumexp over C SMEM values + smooth-L1.
template <int CC, int OO>
__global__ void __launch_bounds__(TP)
loss_kernel(const float* __restrict__ loc_data,
            const float* __restrict__ conf_data,
            const float* __restrict__ priors,
            const float* __restrict__ targets,
            int P, int C) {
    int b = blockIdx.y;
    int tid = threadIdx.x;
    int p0 = blockIdx.x * TP;
    int cnt = min(TP, P - p0);

    __shared__ float sconf[TP * CC];
    __shared__ float sh_t[OO * 5];
    __shared__ unsigned sh_win[OO];
    __shared__ float s_rl[TP / 32], s_rc[TP / 32];
    __shared__ int s_rn[TP / 32];

    if (tid < OO * 5) sh_t[tid] = targets[b * OO * 5 + tid];
    if (tid < OO) {
        unsigned long long kmax = 0ull;
        const unsigned long long* kp = g_keypart + (b * MAXO + tid) * MSPLIT;
#pragma unroll
        for (int s = 0; s < MSPLIT; s++) {
            unsigned long long v = kp[s];
            if (v > kmax) kmax = v;
        }
        sh_win[tid] = 0xFFFFFFFFu - (unsigned)(kmax & 0xFFFFFFFFull);
    }

    {
        size_t base = ((size_t)b * P + p0) * C;
        int tot = cnt * C;
        for (int j = tid; j < tot; j += TP)
            sconf[j] = conf_data[base + j];
    }
    __syncthreads();

    float ll = 0.f, cpos = 0.f;
    int np = 0;

    if (tid < cnt) {
        int p = p0 + tid;
        size_t bp = (size_t)b * P + p;
        float4 pr = ((const float4*)priors)[p];
        float px0 = pr.x - pr.z * 0.5f, py0 = pr.y - pr.w * 0.5f;
        float px1 = pr.x + pr.z * 0.5f, py1 = pr.y + pr.w * 0.5f;
        float areaP = pr.z * pr.w;

        float bestv = -1.f; int ti = 0; int ovr = -1;
#pragma unroll
        for (int o = 0; o < OO; o++) {
            float t0 = sh_t[o * 5 + 0], t1 = sh_t[o * 5 + 1];
            float t2 = sh_t[o * 5 + 2], t3 = sh_t[o * 5 + 3];
            float ltx = fmaxf(t0, px0), lty = fmaxf(t1, py0);
            float rbx = fminf(t2, px1), rby = fminf(t3, py1);
            float iw = fmaxf(rbx - ltx, 0.f), ih = fmaxf(rby - lty, 0.f);
            float inter = iw * ih;
            float areaT = (t2 - t0) * (t3 - t1);
            float ov = __fdividef(inter, areaT + areaP - inter);
            if (ov > bestv) { bestv = ov; ti = o; }      // first (lowest) o on tie
            if (sh_win[o] == (unsigned)p) ovr = o;       // last (highest) o wins
        }
        if (ovr >= 0) { bestv = 2.0f; ti = ovr; }
        int conf_t = (bestv >= 0.5f) ? (int)sh_t[ti * 5 + 4] + 1 : 0;
        bool pos = (conf_t > 0);

        const float* row = sconf + tid * C;
        float m = row[0];
        for (int c = 1; c < C; c++) m = fmaxf(m, row[c]);
        float e = 0.f;
        for (int c = 0; c < C; c++) e += __expf(row[c] - m);
        float lc = m + __logf(e) - row[conf_t];

        g_mined[bp] = pos ? 0.f : lc;
        if (pos) {
            cpos = lc;
            np = 1;
            float mx0 = sh_t[ti * 5 + 0], my0 = sh_t[ti * 5 + 1];
            float mx1 = sh_t[ti * 5 + 2], my1 = sh_t[ti * 5 + 3];
            float g0 = ((mx0 + mx1) * 0.5f - pr.x) / (0.1f * pr.z);
            float g1 = ((my0 + my1) * 0.5f - pr.y) / (0.1f * pr.w);
            float g2 = __logf(fmaxf((mx1 - mx0) / pr.z, 1e-8f)) / 0.2f;
            float g3 = __logf(fmaxf((my1 - my0) / pr.w, 1e-8f)) / 0.2f;
            float4 L = ((const float4*)loc_data)[bp];
            float Ld[4] = {L.x, L.y, L.z, L.w};
            float g4[4] = {g0, g1, g2, g3};
#pragma unroll
            for (int i = 0; i < 4; i++) {
                float d = Ld[i] - g4[i];
                float ad = fabsf(d);
                ll += (ad < 1.f) ? 0.5f * d * d : ad - 0.5f;
            }
        }
    }

    int lane = tid & 31;
#pragma unroll
    for (int off = 16; off; off >>= 1) {
        ll   += __shfl_down_sync(0xFFFFFFFFu, ll, off);
        cpos += __shfl_down_sync(0xFFFFFFFFu, cpos, off);
        np   += __shfl_down_sync(0xFFFFFFFFu, np, off);
    }
    if (lane == 0) { s_rl[tid >> 5] = ll; s_rc[tid >> 5] = cpos; s_rn[tid >> 5] = np; }
    __syncthreads();
    if (tid == 0) {
        float tl = 0.f, tc = 0.f; int tn = 0;
#pragma unroll
        for (int w = 0; w < TP / 32; w++) { tl += s_rl[w]; tc += s_rc[w]; tn += s_rn[w]; }
        if (tl != 0.f)
            atomicAdd(&g_acc_l[b], (unsigned long long)(long long)llrint((double)tl * ACC_SCALE));
        if (tc != 0.f)
            atomicAdd(&g_acc_c[b], (unsigned long long)(long long)llrint((double)tc * ACC_SCALE));
        if (tn) atomicAdd(&g_num_pos[b], tn);
    }
}

// ---------------------------------------------------------------------------
// Per-batch radix-select of top-k mined conf losses. Keys in registers,
// per-warp privatized histograms (no cross-warp atomic chains),
// warp-0 register suffix-scan. Last block finalizes.
__global__ void __launch_bounds__(MB, 1)
mine_kernel(float* __restrict__ out, int P, int B) {
    int b = blockIdx.x;
    int tid = threadIdx.x;
    int lane = tid & 31;
    int wid = tid >> 5;

    __shared__ int hist[32 * HP];      // per-warp rows (padded), ~33.8 KB
    __shared__ int merged[256];
    __shared__ unsigned s_prefix;
    __shared__ int s_kk;
    __shared__ float s_red[MB / 32];
    __shared__ int s_last;

    // keys in registers (values >= 0: bits are order-preserving)
    unsigned key[NIT];
    bool own[NIT];
    const float* mv = g_mined + (size_t)b * P;
#pragma unroll
    for (int i = 0; i < NIT; i++) {
        int p = i * MB + tid;
        own[i] = (p < P);
        key[i] = own[i] ? __float_as_uint(mv[p]) : 0u;
    }

    int np = g_num_pos[b];
    int k = min(3 * np, P - np);
    float negsum = 0.f;

    if (k > 0) {
        int* whist = hist + wid * HP;
        unsigned prefix = 0, pmask = 0;
        int kk = k;
        for (int shift = 24; shift >= 0; shift -= 8) {
#pragma unroll
            for (int j = 0; j < (32 * HP + MB - 1) / MB; j++) {
                int idx = j * MB + tid;
                if (idx < 32 * HP) hist[idx] = 0;
            }
            __syncthreads();
            // warp-aggregated atomics into the warp's private row
#pragma unroll
            for (int i = 0; i < NIT; i++) {
                bool valid = own[i] && ((key[i] & pmask) == prefix);
                unsigned bin = valid ? ((key[i] >> shift) & 0xFFu) : 256u;
                unsigned peers = __match_any_sync(0xFFFFFFFFu, bin);
                if (valid && lane == (__ffs(peers) - 1))
                    atomicAdd(&whist[bin], (int)__popc(peers));
            }
            __syncthreads();
            if (tid < 256) {
                int m = 0;
#pragma unroll
                for (int w = 0; w < 32; w++) m += hist[w * HP + tid];
                merged[tid] = m;
            }
            __syncthreads();
            // warp-0 register suffix scan over 256 bins (lane owns 8 bins)
            if (tid < 32) {
                int base = tid * 8;
                int v[8], suff[8];
#pragma unroll
                for (int i = 0; i < 8; i++) v[i] = merged[base + i];
                int run = 0;
#pragma unroll
                for (int i = 7; i >= 0; i--) { run += v[i]; suff[i] = run; }
                int x = run;
#pragma unroll
                for (int off = 1; off < 32; off <<= 1) {
                    int y = __shfl_down_sync(0xFFFFFFFFu, x, off);
                    if (tid + off < 32) x += y;
                }
                int above = x - run;      // sum over lanes > tid
#pragma unroll
                for (int i = 0; i < 8; i++) {
                    int ss  = suff[i] + above;
                    int ssn = (i < 7) ? suff[i + 1] + above : above;
                    if (ss >= kk && ssn < kk) {
                        s_prefix = prefix | ((unsigned)(base + i) << shift);
                        s_kk = kk - ssn;
                    }
                }
            }
            __syncthreads();
            prefix = s_prefix;
            kk = s_kk;
            pmask |= 0xFFu << shift;
        }

        float lsum = 0.f;
#pragma unroll
        for (int i = 0; i < NIT; i++)
            if (own[i] && key[i] > prefix) lsum += __uint_as_float(key[i]);
#pragma unroll
        for (int off = 16; off; off >>= 1)
            lsum += __shfl_xor_sync(0xFFFFFFFFu, lsum, off);
        if (lane == 0) s_red[wid] = lsum;
        __syncthreads();
        if (tid == 0) {
            float tot = 0.f;
#pragma unroll
            for (int i = 0; i < MB / 32; i++) tot += s_red[i];
            negsum = tot + (float)kk * __uint_as_float(prefix);
        }
    }
    if (tid == 0) {
        g_negsum[b] = negsum;
        __threadfence();
        unsigned done = atomicAdd(&g_done, 1u);
        s_last = (done == (unsigned)(B - 1)) ? 1 : 0;
    }
    __syncthreads();
    if (s_last && tid < 32) {
        double ll = 0.0, lc = 0.0;
        int N = 0;
        for (int bb = tid; bb < B; bb += 32) {
            ll += (double)(long long)g_acc_l[bb];
            lc += (double)(long long)g_acc_c[bb];
            lc += (double)g_negsum[bb] * ACC_SCALE;
            N += g_num_pos[bb];
        }
#pragma unroll
        for (int off = 16; off; off >>= 1) {
            ll += __shfl_down_sync(0xFFFFFFFFu, ll, off);
            lc += __shfl_down_sync(0xFFFFFFFFu, lc, off);
            N  += __shfl_down_sync(0xFFFFFFFFu, N, off);
        }
        if (tid == 0) {
            double fN = (double)N * ACC_SCALE;
            out[0] = (float)(ll / fN);
            out[1] = (float)(lc / fN);
        }
    }
}

// ---------------------------------------------------------------------------
extern "C" void kernel_launch(void* const* d_in, const int* in_sizes, int n_in,
                              void* d_out, int out_size) {
    const float* loc     = (const float*)d_in[0];
    const float* conf    = (const float*)d_in[1];
    const float* priors  = (const float*)d_in[2];
    const float* targets = (const float*)d_in[3];

    int P = in_sizes[2] / 4;
    int B = in_sizes[0] / (P * 4);
    int C = in_sizes[1] / (B * P);
    int O = in_sizes[3] / (B * 5);
    float* out = (float*)d_out;

    dim3 mgrid(MSPLIT, B);
    if (O == 8)
        match_kernel_t<8><<<mgrid, 256>>>(priors, targets, P);
    else
        match_kernel_gen<<<mgrid, 256>>>(priors, targets, P, O);

    dim3 gridB((P + TP - 1) / TP, B);
    if (O == 8 && C == 21)
        loss_kernel<21, 8><<<gridB, TP>>>(loc, conf, priors, targets, P, C);
    else if (C <= 32 && O <= 8)
        loss_kernel<32, 8><<<gridB, TP>>>(loc, conf, priors, targets, P, C);
    else
        loss_kernel<64, MAXO><<<gridB, TP>>>(loc, conf, priors, targets, P, C);

    mine_kernel<<<B, MB>>>(out, P, B);
}